// round 7
// baseline (speedup 1.0000x reference)
#include <cuda_runtime.h>
#include <cstddef>

#define B 16
#define N 1024
#define P 256
#define D 64
#define K 26

// ---- scratch (no allocations allowed; device globals) ----
__device__ float g_importance[N];            // [n]
__device__ float g_scores[B * P];            // [b, p]
__device__ float g_mean[B * P * D];          // [b, p, d]

// ------------------------------------------------------------------
// Kernel 1: importance[j] = mean_i adp[i, j]
// grid 128, block 256 = (8 j-cols) x (32 i-segments of 32 rows).
// 8 consecutive threads read 8 consecutive columns -> one 32B sector.
// ------------------------------------------------------------------
__global__ void __launch_bounds__(256) k_importance(const float* __restrict__ adp) {
    __shared__ float red[32][8];
    int jl   = threadIdx.x & 7;              // 0..7
    int iseg = threadIdx.x >> 3;             // 0..31
    int j    = blockIdx.x * 8 + jl;

    float s = 0.f;
    const float* col = adp + (size_t)(iseg * 32) * N + j;
#pragma unroll 8
    for (int i = 0; i < 32; i++) s += col[(size_t)i * N];
    red[iseg][jl] = s;
    __syncthreads();
    if (iseg == 0) {
        float t = 0.f;
#pragma unroll
        for (int r = 0; r < 32; r++) t += red[r][jl];
        g_importance[j] = t * (1.0f / (float)N);
    }
}

// ------------------------------------------------------------------
// Kernel 2: single fused streaming pass over patches (S=1, no scratch).
// One HALF-WARP per (b, p): 16 lanes x float4 = d=64; the two
// half-warps of a warp take adjacent p -> each warp iteration reads a
// fully contiguous 512B block. 512 CTAs x 128 thr, all resident,
// unroll 8 -> ~57KB outstanding/SM, saturates HBM.
// Writes FINAL g_mean (scaled) and g_scores directly.
// ------------------------------------------------------------------
__global__ void __launch_bounds__(128) k_main(const float* __restrict__ patches) {
    int gwarp = (blockIdx.x * blockDim.x + threadIdx.x) >> 5;   // 0 .. B*P/2-1
    int lane = threadIdx.x & 31;
    int half = lane >> 4;
    int hl   = lane & 15;

    int b  = gwarp / (P / 2);
    int p  = (gwarp % (P / 2)) * 2 + half;

    const float4* base =
        (const float4*)(patches + (((size_t)b * N) * P + p) * (size_t)D) + hl;
    const size_t nstride = (size_t)P * D / 4;   // float4 per n

    float4 ms = make_float4(0.f, 0.f, 0.f, 0.f);
    float score = 0.f;

#pragma unroll 8
    for (int n = 0; n < N; n++) {
        float4 v = __ldcs(base + (size_t)n * nstride);   // streaming, read-once
        ms.x += v.x; ms.y += v.y; ms.z += v.z; ms.w += v.w;
        float sq = v.x * v.x + v.y * v.y + v.z * v.z + v.w * v.w;
        sq += __shfl_xor_sync(0xffffffffu, sq, 8);
        sq += __shfl_xor_sync(0xffffffffu, sq, 4);
        sq += __shfl_xor_sync(0xffffffffu, sq, 2);
        sq += __shfl_xor_sync(0xffffffffu, sq, 1);
        score += sqrtf(sq) * __ldg(g_importance + n);
    }

    const float inv = 1.0f / (float)N;
    ((float4*)g_mean)[((size_t)b * P + p) * (D / 4) + hl] =
        make_float4(ms.x * inv, ms.y * inv, ms.z * inv, ms.w * inv);
    if (hl == 0) g_scores[b * P + p] = score;
}

// ------------------------------------------------------------------
// Kernel 3: fused top-k + anchor gather + replicate.
// Each CTA: rank-count batch b's 256 scores in smem (stable, matches
// jax.lax.top_k: descending, lower index wins ties; broadcast LDS ->
// ~0.7us, redundant across the 64 CTAs per batch but fully parallel),
// then gather the 26x64 anchor block and stream it to 16 n-slots.
// ------------------------------------------------------------------
#define NN_PER_BLOCK 16
#define KD4 (K * D / 4)   // 416 float4 per anchor block

__global__ void __launch_bounds__(256) k_out(float* __restrict__ out) {
    const int chunks = N / NN_PER_BLOCK;          // 64
    int b = blockIdx.x / chunks;
    int c = blockIdx.x % chunks;
    int tid = threadIdx.x;

    __shared__ float  sc[P];
    __shared__ int    tk[K];
    __shared__ float4 sa[KD4];

    sc[tid] = g_scores[b * P + tid];
    __syncthreads();

    {
        float my = sc[tid];
        int rank = 0;
#pragma unroll 8
        for (int q = 0; q < P; q++) {
            float v = sc[q];
            rank += (v > my) || (v == my && q < tid);
        }
        if (rank < K) tk[rank] = tid;
    }
    __syncthreads();

    for (int t = tid; t < KD4; t += blockDim.x) {
        int kk  = t >> 4;          // /(D/4)
        int dd4 = t & 15;
        sa[t] = ((const float4*)g_mean)[((size_t)b * P + tk[kk]) * (D / 4) + dd4];
    }
    __syncthreads();

    // cache this thread's slots in registers (<= 2 per thread)
    int t0 = tid;
    int t1 = tid + 256;
    float4 v0 = sa[t0];
    float4 v1 = (t1 < KD4) ? sa[t1] : make_float4(0, 0, 0, 0);

    float4* obase = (float4*)out + ((size_t)b * N + (size_t)c * NN_PER_BLOCK) * KD4;
#pragma unroll
    for (int nn = 0; nn < NN_PER_BLOCK; nn++) {
        float4* o = obase + (size_t)nn * KD4;
        __stcs(o + t0, v0);
        if (t1 < KD4) __stcs(o + t1, v1);
    }
}

// ------------------------------------------------------------------
extern "C" void kernel_launch(void* const* d_in, const int* in_sizes, int n_in,
                              void* d_out, int out_size) {
    const float* patches = (const float*)d_in[0];
    const float* adp     = (const float*)d_in[1];
    if (n_in >= 2 && in_sizes[0] == N * N && in_sizes[1] == B * N * P * D) {
        const float* t = patches; patches = adp; adp = t;
    }
    float* out = (float*)d_out;

    k_importance<<<128, 256>>>(adp);
    k_main<<<B * (P / 2) * 32 / 128, 128>>>(patches);   // 512 CTAs
    k_out<<<B * (N / NN_PER_BLOCK), 256>>>(out);
}

// round 8
// speedup vs baseline: 2.7863x; 2.7863x over previous
#include <cuda_runtime.h>
#include <cstddef>

#define B 16
#define N 1024
#define P 256
#define D 64
#define K 26
#define S 4                 // n-segments for k_main parallelism (8192 warps)
#define NSEG (N / S)        // 256 n per segment

// ---- scratch (no allocations allowed; device globals) ----
__device__ float g_importance[N];            // [n]
__device__ float g_pscore[S * B * P];        // [s, b*P+p] partial scores
__device__ float g_pmean[S * B * P * D];     // [s, b*P+p, d] partial sums

// ------------------------------------------------------------------
// Kernel 1: importance[j] = mean_i adp[i, j]
// grid 32, block 1024 = (32 j-cols) x (32 i-segments of 32 rows).
// Warp lanes = consecutive j -> 128B coalesced per warp per row.
// ------------------------------------------------------------------
__global__ void __launch_bounds__(1024) k_importance(const float* __restrict__ adp) {
    __shared__ float red[32][33];
    int jl   = threadIdx.x & 31;             // 0..31
    int iseg = threadIdx.x >> 5;             // 0..31
    int j    = blockIdx.x * 32 + jl;

    float s = 0.f;
    const float* col = adp + (size_t)(iseg * 32) * N + j;
#pragma unroll 8
    for (int i = 0; i < 32; i++) s += col[(size_t)i * N];
    red[iseg][jl] = s;
    __syncthreads();
    if (iseg == 0) {
        float t = 0.f;
#pragma unroll
        for (int r = 0; r < 32; r++) t += red[r][jl];
        g_importance[j] = t * (1.0f / (float)N);
    }
}

// ------------------------------------------------------------------
// Kernel 2: fused streaming pass over patches, n-split into S=4
// segments. One HALF-WARP per (seg, b, p): 16 lanes x float4 = d=64;
// the two half-warps of a warp take adjacent p -> each warp iteration
// reads a fully contiguous 512B block. 2048 CTAs x 128 thr = 8192
// warps (empirically required to saturate HBM on this access chain).
// ------------------------------------------------------------------
__global__ void __launch_bounds__(128) k_main(const float* __restrict__ patches) {
    int gwarp = (blockIdx.x * blockDim.x + threadIdx.x) >> 5;   // 0 .. S*B*P/2-1
    int lane = threadIdx.x & 31;
    int half = lane >> 4;
    int hl   = lane & 15;

    int seg   = gwarp / (B * (P / 2));
    int rem   = gwarp % (B * (P / 2));
    int b     = rem / (P / 2);
    int p     = (rem % (P / 2)) * 2 + half;
    int n0    = seg * NSEG;

    const float4* base =
        (const float4*)(patches + (((size_t)b * N + n0) * P + p) * (size_t)D) + hl;
    const size_t nstride = (size_t)P * D / 4;   // float4 per n
    const float* imp = g_importance + n0;

    float4 ms = make_float4(0.f, 0.f, 0.f, 0.f);
    float score = 0.f;

#pragma unroll 8
    for (int n = 0; n < NSEG; n++) {
        float4 v = __ldcs(base + (size_t)n * nstride);   // streaming, read-once
        ms.x += v.x; ms.y += v.y; ms.z += v.z; ms.w += v.w;
        float sq = v.x * v.x + v.y * v.y + v.z * v.z + v.w * v.w;
        sq += __shfl_xor_sync(0xffffffffu, sq, 8);
        sq += __shfl_xor_sync(0xffffffffu, sq, 4);
        sq += __shfl_xor_sync(0xffffffffu, sq, 2);
        sq += __shfl_xor_sync(0xffffffffu, sq, 1);
        score += sqrtf(sq) * __ldg(imp + n);
    }

    size_t bp = (size_t)b * P + p;
    ((float4*)g_pmean)[((size_t)seg * B * P + bp) * (D / 4) + hl] = ms;
    if (hl == 0) g_pscore[(size_t)seg * B * P + bp] = score;
}

// ------------------------------------------------------------------
// Kernel 3: fused score-reduce + top-k + anchor gather + replicate.
// Each CTA (one of 64 per batch):
//   1. reduce the S=4 partial scores per p (identical order in every
//      CTA -> identical rounding -> consistent ranks),
//   2. stable rank-count (matches jax.lax.top_k: descending, lower
//      index wins ties),
//   3. gather the 26x64 anchor block directly from g_pmean partials
//      (L2-hot, reused 64x per batch), scale by 1/N,
//   4. stream-replicate to 16 n-slots.
// ------------------------------------------------------------------
#define NN_PER_BLOCK 16
#define KD4 (K * D / 4)   // 416 float4 per anchor block

__global__ void __launch_bounds__(256) k_out(float* __restrict__ out) {
    const int chunks = N / NN_PER_BLOCK;          // 64
    int b = blockIdx.x / chunks;
    int c = blockIdx.x % chunks;
    int tid = threadIdx.x;

    __shared__ float  sc[P];
    __shared__ int    tk[K];
    __shared__ float4 sa[KD4];

    {
        float my = 0.f;
#pragma unroll
        for (int s = 0; s < S; s++) my += g_pscore[s * B * P + b * P + tid];
        sc[tid] = my;
    }
    __syncthreads();

    {
        float my = sc[tid];
        int rank = 0;
#pragma unroll 8
        for (int q = 0; q < P; q++) {
            float v = sc[q];
            rank += (v > my) || (v == my && q < tid);
        }
        if (rank < K) tk[rank] = tid;
    }
    __syncthreads();

    const int MF4 = B * P * D / 4;                // float4 per segment
    const float inv = 1.0f / (float)N;
    for (int t = tid; t < KD4; t += blockDim.x) {
        int kk  = t >> 4;          // /(D/4)
        int dd4 = t & 15;
        size_t idx = ((size_t)b * P + tk[kk]) * (D / 4) + dd4;
        float4 acc = make_float4(0.f, 0.f, 0.f, 0.f);
#pragma unroll
        for (int s = 0; s < S; s++) {
            float4 v = ((const float4*)g_pmean)[(size_t)s * MF4 + idx];
            acc.x += v.x; acc.y += v.y; acc.z += v.z; acc.w += v.w;
        }
        sa[t] = make_float4(acc.x * inv, acc.y * inv, acc.z * inv, acc.w * inv);
    }
    __syncthreads();

    // cache this thread's slots in registers (<= 2 per thread)
    int t0 = tid;
    int t1 = tid + 256;
    float4 v0 = sa[t0];
    float4 v1 = (t1 < KD4) ? sa[t1] : make_float4(0, 0, 0, 0);

    float4* obase = (float4*)out + ((size_t)b * N + (size_t)c * NN_PER_BLOCK) * KD4;
#pragma unroll
    for (int nn = 0; nn < NN_PER_BLOCK; nn++) {
        float4* o = obase + (size_t)nn * KD4;
        __stcs(o + t0, v0);
        if (t1 < KD4) __stcs(o + t1, v1);
    }
}

// ------------------------------------------------------------------
extern "C" void kernel_launch(void* const* d_in, const int* in_sizes, int n_in,
                              void* d_out, int out_size) {
    const float* patches = (const float*)d_in[0];
    const float* adp     = (const float*)d_in[1];
    if (n_in >= 2 && in_sizes[0] == N * N && in_sizes[1] == B * N * P * D) {
        const float* t = patches; patches = adp; adp = t;
    }
    float* out = (float*)d_out;

    k_importance<<<32, 1024>>>(adp);
    k_main<<<S * B * (P / 2) * 32 / 128, 128>>>(patches);   // 2048 CTAs
    k_out<<<B * (N / NN_PER_BLOCK), 256>>>(out);
}